// round 2
// baseline (speedup 1.0000x reference)
#include <cuda_runtime.h>
#include <math.h>

#define N_NODES 50000
#define N_EDGES 800000
#define HEADS   8
#define ODIM    8
#define HDIM    64            // HEADS*ODIM
#define CLAMP_V 5.0f
#define EPS_V   1e-8f

// ---------------- device scratch (no allocation allowed) ----------------
__device__ __align__(16) float g_Qh[N_NODES * HDIM];
__device__ __align__(16) float g_Kh[N_NODES * HDIM];
__device__ __align__(16) float g_Vh[N_NODES * HDIM];
__device__ __align__(16) float g_s [N_EDGES * HEADS];   // per-edge per-head score, then exp
__device__ __align__(16) float g_m [N_NODES * HEADS];   // segment max
__device__ __align__(16) float g_den[N_NODES * HEADS];  // segment sum
__device__ __align__(16) float g_wV  [N_NODES * HDIM];
__device__ __align__(16) float g_rowV[N_NODES * HDIM];
__device__ int g_src[N_EDGES];
__device__ int g_dst[N_EDGES];
__device__ unsigned g_orhigh;

// ---------------- helpers ----------------
__device__ __forceinline__ void atomicMaxFloat(float* addr, float v) {
    if (v >= 0.0f) atomicMax((int*)addr, __float_as_int(v));
    else           atomicMin((unsigned int*)addr, __float_as_uint(v));
}

__device__ __forceinline__ void redAddV4(float* p, float a, float b, float c, float d) {
    asm volatile("red.global.add.v4.f32 [%0], {%1,%2,%3,%4};"
                 :: "l"(p), "f"(a), "f"(b), "f"(c), "f"(d) : "memory");
}

__device__ __forceinline__ float signed_sqrt(float x) {
    return sqrtf(fmaxf(x, 0.0f) + EPS_V) - sqrtf(fmaxf(-x, 0.0f) + EPS_V);
}

// ---------------- index dtype detection + conversion ----------------
// edge_index may arrive as int64 (reference dtype) or int32 (harness downcast).
// Both have 1.6M elements. Read the first 1.6M 32-bit words as 800k int64s:
// int64 data (values < 50000) -> all high words zero. int32 data -> odd words
// are random indices, OR != 0 essentially surely.
__global__ void k_flag() { g_orhigh = 0u; }

__global__ void k_detect(const unsigned* __restrict__ raw) {
    int i = blockIdx.x * blockDim.x + threadIdx.x;
    unsigned hi = (i < N_EDGES) ? raw[2 * i + 1] : 0u;
    hi = __reduce_or_sync(0xffffffffu, hi);
    if ((threadIdx.x & 31) == 0 && hi) atomicOr(&g_orhigh, hi);
}

__global__ void k_convert(const void* __restrict__ raw) {
    int i = blockIdx.x * blockDim.x + threadIdx.x;
    if (i >= N_EDGES) return;
    if (g_orhigh == 0u) {   // int64
        const long long* p = (const long long*)raw;
        g_src[i] = (int)p[i];
        g_dst[i] = (int)p[N_EDGES + i];
    } else {                // int32
        const int* p = (const int*)raw;
        g_src[i] = p[i];
        g_dst[i] = p[N_EDGES + i];
    }
}

// ---------------- kernel 0: init accumulators ----------------
__global__ void k_init() {
    int i = blockIdx.x * blockDim.x + threadIdx.x;
    if (i < N_NODES * HDIM) { g_wV[i] = 0.0f; g_rowV[i] = 0.0f; }
    if (i < N_NODES * HEADS) { g_m[i] = -CLAMP_V; g_den[i] = 0.0f; }
}

// ---------------- kernel 1: node projections Q,K,V ----------------
// 256 threads = 8 warps, 4 nodes per warp -> 32 nodes/block
__global__ void k_nodeproj(const float* __restrict__ x,
                           const float* __restrict__ Wq, const float* __restrict__ bq,
                           const float* __restrict__ Wk, const float* __restrict__ bk,
                           const float* __restrict__ Wv, const float* __restrict__ bv) {
    __shared__ float sW[64 * 64];
    __shared__ float sA[8][4][64];
    const int tid = threadIdx.x, warp = tid >> 5, lane = tid & 31;
    const int n0 = (blockIdx.x * 8 + warp) * 4;

    #pragma unroll
    for (int n = 0; n < 4; n++) {
        int node = n0 + n; if (node >= N_NODES) node = N_NODES - 1;
        sA[warp][n][lane]      = x[(size_t)node * 64 + lane];
        sA[warp][n][lane + 32] = x[(size_t)node * 64 + lane + 32];
    }

#define PROJ(W, B, OUT) do {                                                  \
    __syncthreads();                                                          \
    for (int i = tid; i < 4096; i += 256) sW[i] = (W)[i];                     \
    __syncthreads();                                                          \
    float b0 = (B)[lane], b1 = (B)[lane + 32];                                \
    float a0c0 = b0, a0c1 = b1, a1c0 = b0, a1c1 = b1;                         \
    float a2c0 = b0, a2c1 = b1, a3c0 = b0, a3c1 = b1;                         \
    _Pragma("unroll 16")                                                      \
    for (int k = 0; k < 64; k++) {                                            \
        float w0 = sW[k * 64 + lane], w1 = sW[k * 64 + lane + 32];            \
        float a0 = sA[warp][0][k], a1 = sA[warp][1][k];                       \
        float a2 = sA[warp][2][k], a3 = sA[warp][3][k];                       \
        a0c0 = fmaf(a0, w0, a0c0); a0c1 = fmaf(a0, w1, a0c1);                 \
        a1c0 = fmaf(a1, w0, a1c0); a1c1 = fmaf(a1, w1, a1c1);                 \
        a2c0 = fmaf(a2, w0, a2c0); a2c1 = fmaf(a2, w1, a2c1);                 \
        a3c0 = fmaf(a3, w0, a3c0); a3c1 = fmaf(a3, w1, a3c1);                 \
    }                                                                         \
    if (n0 + 0 < N_NODES) { (OUT)[(size_t)(n0+0)*64+lane]=a0c0; (OUT)[(size_t)(n0+0)*64+lane+32]=a0c1; } \
    if (n0 + 1 < N_NODES) { (OUT)[(size_t)(n0+1)*64+lane]=a1c0; (OUT)[(size_t)(n0+1)*64+lane+32]=a1c1; } \
    if (n0 + 2 < N_NODES) { (OUT)[(size_t)(n0+2)*64+lane]=a2c0; (OUT)[(size_t)(n0+2)*64+lane+32]=a2c1; } \
    if (n0 + 3 < N_NODES) { (OUT)[(size_t)(n0+3)*64+lane]=a3c0; (OUT)[(size_t)(n0+3)*64+lane+32]=a3c1; } \
} while (0)

    PROJ(Wq, bq, g_Qh);
    PROJ(Wk, bk, g_Kh);
    PROJ(Wv, bv, g_Vh);
#undef PROJ
}

// ---------------- kernel 2: edge pass 1 ----------------
// E_proj GEMM, signed-sqrt score, wE write, per-head s + atomicMax.
// Column layout: E_proj reshaped (E, HEADS, 2*ODIM) -> for output col j = h*8+d:
//   E_w at GEMM column h*16+d, E_b at h*16+8+d.
// Lane j in 0..31 handles j and j+32 (heads h0 and h0+4): GEMM columns
//   cw, cw+64 (E_w) and cw+8, cw+72 (E_b) with cw = (lane>>3)*16 + (lane&7).
__global__ void k_edge1(const float* __restrict__ edge_attr,
                        const float* __restrict__ We, const float* __restrict__ be,
                        const float* __restrict__ Aw,
                        float* __restrict__ wE_out) {
    __shared__ float sWe[64 * 128];   // 32 KB, row-major (k, j)
    __shared__ float sbe[128];
    __shared__ float sAw[64];         // Aw[d*8+h]
    __shared__ float sA[4][4][64];    // per-warp edge rows

    const int tid = threadIdx.x, warp = tid >> 5, lane = tid & 31;

    for (int i = tid; i < 64 * 128; i += 128) sWe[i] = We[i];
    if (tid < 128) sbe[tid] = be[tid];
    if (tid < 64)  sAw[tid] = Aw[tid];

    const int e0 = (blockIdx.x * 4 + warp) * 4;
    #pragma unroll
    for (int n = 0; n < 4; n++) {
        size_t base = (size_t)(e0 + n) * 64;
        sA[warp][n][lane]      = edge_attr[base + lane];
        sA[warp][n][lane + 32] = edge_attr[base + lane + 32];
    }
    __syncthreads();

    const int d0 = lane & 7;
    const int h0 = lane >> 3;            // head for col j=lane; j=lane+32 -> h0+4
    const int cw = (h0 << 4) + d0;       // E_w column for (h0, d0)

    // acc[n][0]=E_w(j), [1]=E_w(j+32), [2]=E_b(j), [3]=E_b(j+32)
    float acc[4][4];
    {
        float b0 = sbe[cw], b1 = sbe[cw + 64], b2 = sbe[cw + 8], b3 = sbe[cw + 72];
        #pragma unroll
        for (int n = 0; n < 4; n++) { acc[n][0]=b0; acc[n][1]=b1; acc[n][2]=b2; acc[n][3]=b3; }
    }

    #pragma unroll 8
    for (int k = 0; k < 64; k++) {
        float w0 = sWe[k * 128 + cw];
        float w1 = sWe[k * 128 + cw + 64];
        float w2 = sWe[k * 128 + cw + 8];
        float w3 = sWe[k * 128 + cw + 72];
        #pragma unroll
        for (int n = 0; n < 4; n++) {
            float a = sA[warp][n][k];
            acc[n][0] = fmaf(a, w0, acc[n][0]);
            acc[n][1] = fmaf(a, w1, acc[n][1]);
            acc[n][2] = fmaf(a, w2, acc[n][2]);
            acc[n][3] = fmaf(a, w3, acc[n][3]);
        }
    }

    const float aw0 = sAw[d0 * 8 + h0];
    const float aw1 = sAw[d0 * 8 + h0 + 4];

    #pragma unroll
    for (int n = 0; n < 4; n++) {
        int e = e0 + n;
        int src = g_src[e];
        int dst = g_dst[e];

        float kq0 = g_Kh[(size_t)src * 64 + lane]      + g_Qh[(size_t)dst * 64 + lane];
        float kq1 = g_Kh[(size_t)src * 64 + lane + 32] + g_Qh[(size_t)dst * 64 + lane + 32];
        float sc0 = signed_sqrt(kq0 * acc[n][0]) + acc[n][2];
        float sc1 = signed_sqrt(kq1 * acc[n][1]) + acc[n][3];

        wE_out[(size_t)e * 64 + lane]      = sc0;
        wE_out[(size_t)e * 64 + lane + 32] = sc1;

        // per-head reduction over d (8-lane groups)
        float p0 = sc0 * aw0;
        float p1 = sc1 * aw1;
        #pragma unroll
        for (int off = 4; off > 0; off >>= 1) {
            p0 += __shfl_down_sync(0xffffffffu, p0, off, 8);
            p1 += __shfl_down_sync(0xffffffffu, p1, off, 8);
        }
        if (d0 == 0) {
            float s0 = fminf(fmaxf(p0, -CLAMP_V), CLAMP_V);
            float s1 = fminf(fmaxf(p1, -CLAMP_V), CLAMP_V);
            g_s[(size_t)e * 8 + h0]     = s0;
            g_s[(size_t)e * 8 + h0 + 4] = s1;
            atomicMaxFloat(&g_m[(size_t)dst * 8 + h0],     s0);
            atomicMaxFloat(&g_m[(size_t)dst * 8 + h0 + 4], s1);
        }
    }
}

// ---------------- kernel 3: exp + denominator ----------------
__global__ void k_soft() {
    int i = blockIdx.x * blockDim.x + threadIdx.x;
    if (i >= N_EDGES * HEADS) return;
    int e = i >> 3, h = i & 7;
    int dst = g_dst[e];
    float v = expf(g_s[i] - g_m[(size_t)dst * 8 + h]);
    g_s[i] = v;
    atomicAdd(&g_den[(size_t)dst * 8 + h], v);
}

// ---------------- kernel 4: attn * V and attn * e_t scatter ----------------
// thread handles (edge, 4 consecutive cols): 16 threads/edge
__global__ void k_edge2(const float* __restrict__ wE) {
    int i = blockIdx.x * blockDim.x + threadIdx.x;
    if (i >= N_EDGES * 16) return;
    int e = i >> 4, q = i & 15;
    int j0 = q * 4;
    int h = q >> 1;
    int src = g_src[e];
    int dst = g_dst[e];
    float attn = g_s[(size_t)e * 8 + h] / (g_den[(size_t)dst * 8 + h] + 1e-16f);

    float4 v  = *reinterpret_cast<const float4*>(&g_Vh[(size_t)src * 64 + j0]);
    redAddV4(&g_wV[(size_t)dst * 64 + j0], v.x * attn, v.y * attn, v.z * attn, v.w * attn);

    float4 et = *reinterpret_cast<const float4*>(&wE[(size_t)e * 64 + j0]);
    redAddV4(&g_rowV[(size_t)dst * 64 + j0], et.x * attn, et.y * attn, et.z * attn, et.w * attn);
}

// ---------------- kernel 5: finalize wV = wV_acc + rowV @ VeRow ----------------
__global__ void k_final(const float* __restrict__ VeRow, float* __restrict__ wV_out) {
    int i = blockIdx.x * blockDim.x + threadIdx.x;
    if (i >= N_NODES * HDIM) return;
    int n = i >> 6, j = i & 63;
    int h = j >> 3, c = j & 7;
    float acc = g_wV[i];
    const float* rv = &g_rowV[(size_t)n * 64 + h * 8];
    #pragma unroll
    for (int d = 0; d < 8; d++)
        acc = fmaf(rv[d], __ldg(&VeRow[d * 64 + h * 8 + c]), acc);
    wV_out[i] = acc;
}

// ---------------- launch ----------------
extern "C" void kernel_launch(void* const* d_in, const int* in_sizes, int n_in,
                              void* d_out, int out_size) {
    const float* x         = (const float*)d_in[0];
    const float* edge_attr = (const float*)d_in[1];
    const void*  ei_raw    = d_in[2];
    const float* Wq = (const float*)d_in[3];
    const float* bq = (const float*)d_in[4];
    const float* Wk = (const float*)d_in[5];
    const float* bk = (const float*)d_in[6];
    const float* We = (const float*)d_in[7];
    const float* be = (const float*)d_in[8];
    const float* Wv = (const float*)d_in[9];
    const float* bv = (const float*)d_in[10];
    const float* Aw = (const float*)d_in[11];
    const float* VeRow = (const float*)d_in[12];

    float* out    = (float*)d_out;
    float* wV_out = out;                               // N_NODES*64
    float* wE_out = out + (size_t)N_NODES * HDIM;      // N_EDGES*64

    k_flag<<<1, 1>>>();
    k_detect<<<(N_EDGES + 255) / 256, 256>>>((const unsigned*)ei_raw);
    k_convert<<<(N_EDGES + 255) / 256, 256>>>(ei_raw);
    k_init<<<(N_NODES * HDIM + 255) / 256, 256>>>();
    k_nodeproj<<<(N_NODES + 31) / 32, 256>>>(x, Wq, bq, Wk, bk, Wv, bv);
    k_edge1<<<N_EDGES / 16, 128>>>(edge_attr, We, be, Aw, wE_out);
    k_soft<<<(N_EDGES * HEADS + 255) / 256, 256>>>();
    k_edge2<<<(N_EDGES * 16 + 255) / 256, 256>>>(wE_out);
    k_final<<<(N_NODES * HDIM + 255) / 256, 256>>>(VeRow, wV_out);
}

// round 3
// speedup vs baseline: 1.4746x; 1.4746x over previous
#include <cuda_runtime.h>
#include <math.h>

#define N_NODES 50000
#define N_EDGES 800000
#define HEADS   8
#define ODIM    8
#define HDIM    64
#define CLAMP_V 5.0f
#define EPS_V   1e-8f
#define TILES   (N_EDGES / 32)      // 25000 tiles of 32 edges
#define EDGE_GRID 444               // 148 SMs * 3 blocks

// ---------------- device scratch ----------------
__device__ __align__(16) float g_Qh[N_NODES * HDIM];
__device__ __align__(16) float g_Kh[N_NODES * HDIM];
__device__ __align__(16) float g_Vh[N_NODES * HDIM];
__device__ __align__(16) float g_den[N_NODES * HEADS];   // sum of exp(s) per (node, head)
__device__ __align__(16) float g_wV  [N_NODES * HDIM];   // unnormalized sum exp*V
__device__ __align__(16) float g_rowV[N_NODES * HDIM];   // unnormalized sum exp*e_t
__device__ int g_src[N_EDGES];
__device__ int g_dst[N_EDGES];
__device__ unsigned g_orhigh;

// ---------------- helpers ----------------
__device__ __forceinline__ void redAddV4(float* p, float a, float b, float c, float d) {
    asm volatile("red.global.add.v4.f32 [%0], {%1,%2,%3,%4};"
                 :: "l"(p), "f"(a), "f"(b), "f"(c), "f"(d) : "memory");
}
__device__ __forceinline__ void ffma2(unsigned long long& acc,
                                      unsigned long long a, unsigned long long b) {
    asm("fma.rn.f32x2 %0, %1, %2, %0;" : "+l"(acc) : "l"(a), "l"(b));
}
__device__ __forceinline__ unsigned long long pack2(float lo, float hi) {
    unsigned long long r;
    asm("mov.b64 %0, {%1,%2};" : "=l"(r) : "f"(lo), "f"(hi));
    return r;
}
__device__ __forceinline__ float2 unpack2(unsigned long long v) {
    float2 r;
    asm("mov.b64 {%0,%1}, %2;" : "=f"(r.x), "=f"(r.y) : "l"(v));
    return r;
}
__device__ __forceinline__ float signed_sqrt(float x) {
    return sqrtf(fmaxf(x, 0.0f) + EPS_V) - sqrtf(fmaxf(-x, 0.0f) + EPS_V);
}

// ---------------- index dtype detection + conversion ----------------
__global__ void k_flag() { g_orhigh = 0u; }

__global__ void k_detect(const unsigned* __restrict__ raw) {
    int i = blockIdx.x * blockDim.x + threadIdx.x;
    unsigned hi = (i < N_EDGES) ? raw[2 * i + 1] : 0u;
    hi = __reduce_or_sync(0xffffffffu, hi);
    if ((threadIdx.x & 31) == 0 && hi) atomicOr(&g_orhigh, hi);
}

__global__ void k_convert(const void* __restrict__ raw) {
    int i = blockIdx.x * blockDim.x + threadIdx.x;
    if (i >= N_EDGES) return;
    if (g_orhigh == 0u) {   // int64 input
        const long long* p = (const long long*)raw;
        g_src[i] = (int)p[i];
        g_dst[i] = (int)p[N_EDGES + i];
    } else {                // int32 input
        const int* p = (const int*)raw;
        g_src[i] = p[i];
        g_dst[i] = p[N_EDGES + i];
    }
}

// ---------------- init accumulators (every launch) ----------------
__global__ void k_init() {
    int i = blockIdx.x * blockDim.x + threadIdx.x;
    if (i < N_NODES * HDIM) { g_wV[i] = 0.0f; g_rowV[i] = 0.0f; }
    if (i < N_NODES * HEADS) g_den[i] = 0.0f;
}

// ---------------- node projections Q,K,V ----------------
__global__ void k_nodeproj(const float* __restrict__ x,
                           const float* __restrict__ Wq, const float* __restrict__ bq,
                           const float* __restrict__ Wk, const float* __restrict__ bk,
                           const float* __restrict__ Wv, const float* __restrict__ bv) {
    __shared__ float sW[64 * 64];
    __shared__ float sA[8][4][64];
    const int tid = threadIdx.x, warp = tid >> 5, lane = tid & 31;
    const int n0 = (blockIdx.x * 8 + warp) * 4;

    #pragma unroll
    for (int n = 0; n < 4; n++) {
        int node = n0 + n; if (node >= N_NODES) node = N_NODES - 1;
        sA[warp][n][lane]      = x[(size_t)node * 64 + lane];
        sA[warp][n][lane + 32] = x[(size_t)node * 64 + lane + 32];
    }

#define PROJ(W, B, OUT) do {                                                  \
    __syncthreads();                                                          \
    for (int i = tid; i < 4096; i += 256) sW[i] = (W)[i];                     \
    __syncthreads();                                                          \
    float b0 = (B)[lane], b1 = (B)[lane + 32];                                \
    float a0c0 = b0, a0c1 = b1, a1c0 = b0, a1c1 = b1;                         \
    float a2c0 = b0, a2c1 = b1, a3c0 = b0, a3c1 = b1;                         \
    _Pragma("unroll 16")                                                      \
    for (int k = 0; k < 64; k++) {                                            \
        float w0 = sW[k * 64 + lane], w1 = sW[k * 64 + lane + 32];            \
        float a0 = sA[warp][0][k], a1 = sA[warp][1][k];                       \
        float a2 = sA[warp][2][k], a3 = sA[warp][3][k];                       \
        a0c0 = fmaf(a0, w0, a0c0); a0c1 = fmaf(a0, w1, a0c1);                 \
        a1c0 = fmaf(a1, w0, a1c0); a1c1 = fmaf(a1, w1, a1c1);                 \
        a2c0 = fmaf(a2, w0, a2c0); a2c1 = fmaf(a2, w1, a2c1);                 \
        a3c0 = fmaf(a3, w0, a3c0); a3c1 = fmaf(a3, w1, a3c1);                 \
    }                                                                         \
    if (n0 + 0 < N_NODES) { (OUT)[(size_t)(n0+0)*64+lane]=a0c0; (OUT)[(size_t)(n0+0)*64+lane+32]=a0c1; } \
    if (n0 + 1 < N_NODES) { (OUT)[(size_t)(n0+1)*64+lane]=a1c0; (OUT)[(size_t)(n0+1)*64+lane+32]=a1c1; } \
    if (n0 + 2 < N_NODES) { (OUT)[(size_t)(n0+2)*64+lane]=a2c0; (OUT)[(size_t)(n0+2)*64+lane+32]=a2c1; } \
    if (n0 + 3 < N_NODES) { (OUT)[(size_t)(n0+3)*64+lane]=a3c0; (OUT)[(size_t)(n0+3)*64+lane+32]=a3c1; } \
} while (0)

    PROJ(Wq, bq, g_Qh);
    PROJ(Wk, bk, g_Kh);
    PROJ(Wv, bv, g_Vh);
#undef PROJ
}

// ---------------- fused edge kernel ----------------
// Persistent blocks: pack We once, then block-stride over 32-edge tiles.
// Per edge: E_proj (FFMA2 GEMM) -> signed-sqrt score -> wE write ->
// per-head exp -> den red + unnormalized exp*V / exp*e_t scatter (red.v4).
// Column map: score col j=lane <-> GEMM cols cw (E_w) / cw+8 (E_b);
// j=lane+32 <-> cw+64 / cw+72, with cw=(lane>>3)*16+(lane&7).
__global__ void __launch_bounds__(256, 3)
k_edge(const float* __restrict__ edge_attr,
       const float* __restrict__ We, const float* __restrict__ be,
       const float* __restrict__ Aw,
       float* __restrict__ wE_out) {
    __shared__ float sWp[64 * 128];   // packed weights: [k][l*4 + {w0,w1,b0,b1}]  32KB
    __shared__ float sA[8][4][64];    // edge attrs per warp                        8KB
    __shared__ float sP[8][4][8];     // exp(s) per (warp, edge, head)              1KB

    const int tid = threadIdx.x, warp = tid >> 5, lane = tid & 31;
    const int d0 = lane & 7, h0 = lane >> 3;
    const int cw = (h0 << 4) + d0;

    // pack weights once per block: slot r: 0->cw, 1->cw+64, 2->cw+8, 3->cw+72
    for (int i = tid; i < 64 * 128; i += 256) {
        int k = i >> 7, t = i & 127, l = t >> 2, r = t & 3;
        int lcw = ((l >> 3) << 4) + (l & 7);
        int col = lcw + ((r == 0) ? 0 : (r == 1) ? 64 : (r == 2) ? 8 : 72);
        sWp[i] = We[k * 128 + col];
    }
    __syncthreads();

    const unsigned long long beW = pack2(be[cw], be[cw + 64]);
    const unsigned long long beB = pack2(be[cw + 8], be[cw + 72]);
    const float aw0 = Aw[d0 * 8 + h0];
    const float aw1 = Aw[d0 * 8 + h0 + 4];

    for (int tile = blockIdx.x; tile < TILES; tile += gridDim.x) {
        const int e0 = tile * 32 + warp * 4;

        // phase A: load 4 edge rows into smem
        #pragma unroll
        for (int n = 0; n < 4; n++) {
            size_t base = (size_t)(e0 + n) * 64;
            sA[warp][n][lane]      = edge_attr[base + lane];
            sA[warp][n][lane + 32] = edge_attr[base + lane + 32];
        }
        __syncwarp();

        // phase GEMM: FFMA2, 8 packed FMAs per k per thread
        unsigned long long accW[4], accB[4];
        #pragma unroll
        for (int n = 0; n < 4; n++) { accW[n] = beW; accB[n] = beB; }

        #pragma unroll 8
        for (int k = 0; k < 64; k++) {
            ulonglong2 w = *reinterpret_cast<const ulonglong2*>(&sWp[k * 128 + lane * 4]);
            #pragma unroll
            for (int n = 0; n < 4; n++) {
                float a = sA[warp][n][k];
                unsigned long long a2 = pack2(a, a);
                ffma2(accW[n], a2, w.x);
                ffma2(accB[n], a2, w.y);
            }
        }

        // phase B: scores, wE write, per-head exp, denominator
        int srcs[4], dsts[4];
        #pragma unroll
        for (int n = 0; n < 4; n++) {
            int e = e0 + n;
            int src = g_src[e], dst = g_dst[e];
            srcs[n] = src; dsts[n] = dst;
            float2 ew = unpack2(accW[n]);
            float2 eb = unpack2(accB[n]);
            float kq0 = g_Kh[(size_t)src * 64 + lane]      + g_Qh[(size_t)dst * 64 + lane];
            float kq1 = g_Kh[(size_t)src * 64 + lane + 32] + g_Qh[(size_t)dst * 64 + lane + 32];
            float sc0 = signed_sqrt(kq0 * ew.x) + eb.x;
            float sc1 = signed_sqrt(kq1 * ew.y) + eb.y;

            wE_out[(size_t)e * 64 + lane]      = sc0;
            wE_out[(size_t)e * 64 + lane + 32] = sc1;

            float p0 = sc0 * aw0;
            float p1 = sc1 * aw1;
            #pragma unroll
            for (int off = 4; off > 0; off >>= 1) {
                p0 += __shfl_xor_sync(0xffffffffu, p0, off);
                p1 += __shfl_xor_sync(0xffffffffu, p1, off);
            }
            p0 = expf(fminf(fmaxf(p0, -CLAMP_V), CLAMP_V));
            p1 = expf(fminf(fmaxf(p1, -CLAMP_V), CLAMP_V));
            if (d0 == 0) {
                sP[warp][n][h0]     = p0;
                sP[warp][n][h0 + 4] = p1;
                atomicAdd(&g_den[(size_t)dst * 8 + h0],     p0);
                atomicAdd(&g_den[(size_t)dst * 8 + h0 + 4], p1);
            }
        }
        __syncwarp();

        // phase C: scatter unnormalized numerators.
        // lanes 0-15: exp*V -> g_wV; lanes 16-31: exp*e_t -> g_rowV
        // (e_t read back from just-written wE lines: L1/L2 hit)
        const int q  = lane & 15;
        const int j0 = q * 4;
        const int hq = q >> 1;
        #pragma unroll
        for (int n = 0; n < 4; n++) {
            float p = sP[warp][n][hq];
            int dst = dsts[n];
            if (lane < 16) {
                float4 v = *reinterpret_cast<const float4*>(&g_Vh[(size_t)srcs[n] * 64 + j0]);
                redAddV4(&g_wV[(size_t)dst * 64 + j0], v.x * p, v.y * p, v.z * p, v.w * p);
            } else {
                float4 et = *reinterpret_cast<const float4*>(&wE_out[(size_t)(e0 + n) * 64 + j0]);
                redAddV4(&g_rowV[(size_t)dst * 64 + j0], et.x * p, et.y * p, et.z * p, et.w * p);
            }
        }
    }
}

// ---------------- finalize: wV = (wV_raw + rowV_raw @ VeRow) / den ----------------
__global__ void k_final(const float* __restrict__ VeRow, float* __restrict__ wV_out) {
    int i = blockIdx.x * blockDim.x + threadIdx.x;
    if (i >= N_NODES * HDIM) return;
    int n = i >> 6, j = i & 63;
    int h = j >> 3, c = j & 7;
    float inv = 1.0f / (g_den[(size_t)n * 8 + h] + 1e-16f);
    float acc = g_wV[i];
    const float* rv = &g_rowV[(size_t)n * 64 + h * 8];
    #pragma unroll
    for (int d = 0; d < 8; d++)
        acc = fmaf(rv[d], __ldg(&VeRow[d * 64 + h * 8 + c]), acc);
    wV_out[i] = acc * inv;
}

// ---------------- launch ----------------
extern "C" void kernel_launch(void* const* d_in, const int* in_sizes, int n_in,
                              void* d_out, int out_size) {
    const float* x         = (const float*)d_in[0];
    const float* edge_attr = (const float*)d_in[1];
    const void*  ei_raw    = d_in[2];
    const float* Wq = (const float*)d_in[3];
    const float* bq = (const float*)d_in[4];
    const float* Wk = (const float*)d_in[5];
    const float* bk = (const float*)d_in[6];
    const float* We = (const float*)d_in[7];
    const float* be = (const float*)d_in[8];
    const float* Wv = (const float*)d_in[9];
    const float* bv = (const float*)d_in[10];
    const float* Aw = (const float*)d_in[11];
    const float* VeRow = (const float*)d_in[12];

    float* out    = (float*)d_out;
    float* wV_out = out;                               // N_NODES*64
    float* wE_out = out + (size_t)N_NODES * HDIM;      // N_EDGES*64

    k_flag<<<1, 1>>>();
    k_detect<<<(N_EDGES + 255) / 256, 256>>>((const unsigned*)ei_raw);
    k_convert<<<(N_EDGES + 255) / 256, 256>>>(ei_raw);
    k_init<<<(N_NODES * HDIM + 255) / 256, 256>>>();
    k_nodeproj<<<(N_NODES + 31) / 32, 256>>>(x, Wq, bq, Wk, bk, Wv, bv);
    k_edge<<<EDGE_GRID, 256>>>(edge_attr, We, be, Aw, wE_out);
    k_final<<<(N_NODES * HDIM + 255) / 256, 256>>>(VeRow, wV_out);
}